// round 5
// baseline (speedup 1.0000x reference)
#include <cuda_runtime.h>
#include <cuda_bf16.h>
#include <cstdint>

#define Npts 100000
#define Mpts 100000
#define NNB 32
#define KP 15
#define FD 64
#define CD 64

constexpr int MT = 64;             // output points per block
constexpr int THREADS = 256;
constexpr int GRID = (Mpts + MT - 1) / MT;   // 1563

constexpr int ASTRIDE_B = 144;     // bytes per tile row (odd multiple of 16B -> conflict-free ldmatrix)
constexpr int ASTRIDE_E = 72;      // bf16 elems per row
constexpr int BTILE_BYTES = 64 * ASTRIDE_B;  // 9216

// ---- shared memory byte offsets ----
constexpr int A_HI = 0;            // [64][72] bf16 = 9216
constexpr int A_LO = 9216;
constexpr int B_HI = 18432;        // [64][72] bf16 = 9216
constexpr int B_LO = 27648;
constexpr int S_PQ = 36864;        // [64][32] float4 (dx,dy,dz, idx-bits) = 32768
constexpr int S_KM = 69632;        // [64][16] u32 per-(m,k) neighbor bitmask = 4096
constexpr int S_KP = 73728;        // [15][4] f32 = 240 -> 256
constexpr int SMEM_TOTAL = 73984;

// pre-transposed, padded B tiles: [k][c=64][f=72] bf16 (hi / lo split)
__device__ __align__(16) unsigned short g_Vt_hi[KP * 64 * ASTRIDE_E];
__device__ __align__(16) unsigned short g_Vt_lo[KP * 64 * ASTRIDE_E];

__device__ __forceinline__ uint32_t smem_u32(const void* p) {
    uint32_t a;
    asm("{ .reg .u64 t; cvta.to.shared.u64 t, %1; cvt.u32.u64 %0, t; }" : "=r"(a) : "l"(p));
    return a;
}

__device__ __forceinline__ void ldmx4(uint32_t* r, uint32_t addr) {
    asm volatile("ldmatrix.sync.aligned.m8n8.x4.shared.b16 {%0,%1,%2,%3}, [%4];"
                 : "=r"(r[0]), "=r"(r[1]), "=r"(r[2]), "=r"(r[3]) : "r"(addr));
}

__device__ __forceinline__ void mma16816(float* d, const uint32_t* a, const uint32_t* b) {
    asm volatile(
        "mma.sync.aligned.m16n8k16.row.col.f32.bf16.bf16.f32 "
        "{%0,%1,%2,%3}, {%4,%5,%6,%7}, {%8,%9}, {%0,%1,%2,%3};"
        : "+f"(d[0]), "+f"(d[1]), "+f"(d[2]), "+f"(d[3])
        : "r"(a[0]), "r"(a[1]), "r"(a[2]), "r"(a[3]), "r"(b[0]), "r"(b[1]));
}

__device__ __forceinline__ void cp16(uint32_t dst, const void* src) {
    asm volatile("cp.async.cg.shared.global [%0], [%1], 16;" :: "r"(dst), "l"(src));
}
#define CP_COMMIT() asm volatile("cp.async.commit_group;" ::: "memory")
#define CP_WAIT0()  asm volatile("cp.async.wait_group 0;" ::: "memory")

// ------------- prologue: transpose kvals [k][f][c] -> padded bf16 hi/lo [k][c][72] -------------
__global__ void vt_prep(const float* __restrict__ kv) {
    int id = blockIdx.x * blockDim.x + threadIdx.x;
    if (id >= KP * 64 * 64) return;
    int k = id >> 12;
    int rem = id & 4095;
    int f = rem >> 6;
    int c = rem & 63;
    float v = kv[id];
    __nv_bfloat16 hb = __float2bfloat16_rn(v);
    __nv_bfloat16 lb = __float2bfloat16_rn(v - __bfloat162float(hb));
    int dst = (k * 64 + c) * ASTRIDE_E + f;
    g_Vt_hi[dst] = __bfloat16_as_ushort(hb);
    g_Vt_lo[dst] = __bfloat16_as_ushort(lb);
}

// ------------------------------- main kernel -------------------------------
__global__ void __launch_bounds__(THREADS, 3)
kpconv_mma(const float* __restrict__ points,
           const float* __restrict__ features,
           const float* __restrict__ outpts,
           const int*   __restrict__ nbr,
           const float* __restrict__ kpts,
           float*       __restrict__ out)
{
    extern __shared__ char smem[];
    const uint32_t smem_base = smem_u32(smem);
    float*    s_kp = reinterpret_cast<float*>(smem + S_KP);
    unsigned* s_km = reinterpret_cast<unsigned*>(smem + S_KM);
    float4*   s_pq = reinterpret_cast<float4*>(smem + S_PQ);

    const int tid = threadIdx.x;
    const int wid = tid >> 5;
    const int ln  = tid & 31;
    const int m0  = blockIdx.x * MT;

    if (tid < KP * 3) s_kp[(tid / 3) * 4 + (tid % 3)] = kpts[tid];
    __syncthreads();

    // ---- setup: pq vectors + per-(m,k) neighbor bitmasks ----
    #pragma unroll 1
    for (int j = 0; j < (MT * NNB) / THREADS; ++j) {
        const int i = j * THREADS + tid;
        const int m = i >> 5;                 // constant within a warp
        const int gm = m0 + m;
        float dx, dy, dz;
        int gi = 0;
        if (gm < Mpts) {
            gi = nbr[(size_t)gm * NNB + ln];
            const float qx = outpts[gm * 3 + 0];
            const float qy = outpts[gm * 3 + 1];
            const float qz = outpts[gm * 3 + 2];
            dx = __ldg(points + 3 * (size_t)gi + 0) - qx;
            dy = __ldg(points + 3 * (size_t)gi + 1) - qy;
            dz = __ldg(points + 3 * (size_t)gi + 2) - qz;
        } else {
            dx = dy = dz = 1e18f;
        }
        s_pq[i] = make_float4(dx, dy, dz, __int_as_float(gi));
        #pragma unroll
        for (int k = 0; k < KP; ++k) {
            const float ex = dx - s_kp[k * 4 + 0];
            const float ey = dy - s_kp[k * 4 + 1];
            const float ez = dz - s_kp[k * 4 + 2];
            const float d2 = ex * ex + ey * ey + ez * ez;
            const unsigned bal = __ballot_sync(0xffffffffu, d2 < 1.0f);
            if (ln == 0) s_km[m * 16 + k] = bal;
        }
    }

    // ---- per-thread mappings ----
    const int wm = (wid & 3) * 16;      // mma warp tile: rows
    const int wc = (wid >> 2) * 32;     // mma warp tile: cols
    const int arow = wm + (ln & 7) + ((ln >> 3) & 1) * 8;
    const uint32_t aoff = (uint32_t)(arow * ASTRIDE_B + ((ln >> 4) & 1) * 16);
    const uint32_t aaddr_hi = smem_base + A_HI + aoff;
    const uint32_t aaddr_lo = smem_base + A_LO + aoff;
    const int brow = wc + (ln & 7) + ((ln >> 4) & 1) * 8;
    const uint32_t boff = (uint32_t)(brow * ASTRIDE_B + ((ln >> 3) & 1) * 16);
    const uint32_t baddr_hi = smem_base + B_HI + boff;
    const uint32_t baddr_lo = smem_base + B_LO + boff;

    float Dacc[4][4];
    #pragma unroll
    for (int a = 0; a < 4; ++a)
        #pragma unroll
        for (int b = 0; b < 4; ++b) Dacc[a][b] = 0.f;

    __syncthreads();   // masks + pq visible

    // ---- pre-issue B(0) copy (overlaps with gather(0)) ----
    {
        const char* srcH = reinterpret_cast<const char*>(g_Vt_hi);
        const char* srcL = reinterpret_cast<const char*>(g_Vt_lo);
        #pragma unroll
        for (int r = tid * 16; r < BTILE_BYTES; r += THREADS * 16) {
            cp16(smem_base + B_HI + r, srcH + r);
            cp16(smem_base + B_LO + r, srcL + r);
        }
        CP_COMMIT();
    }

    #pragma unroll 1
    for (int k = 0; k < KP; ++k) {
        const float kpx = s_kp[k * 4 + 0];
        const float kpy = s_kp[k * 4 + 1];
        const float kpz = s_kp[k * 4 + 2];

        // ---------- warp-uniform gather: warp owns m = wid*8 .. wid*8+7 ----------
        // lane ln owns features 2ln, 2ln+1 of every m; each active row is one
        // coalesced warp-wide LDG.64 (2 L1 wavefronts per 256B row).
        float acc[8][2];
        #pragma unroll
        for (int mi = 0; mi < 8; ++mi) { acc[mi][0] = 0.f; acc[mi][1] = 0.f; }

        #pragma unroll 1
        for (int mi = 0; mi < 8; ++mi) {
            const int m = wid * 8 + mi;
            unsigned mask = s_km[m * 16 + k];         // identical in all lanes
            const float4* pqm = s_pq + m * 32;
            while (mask) {
                const int n0 = __ffs(mask) - 1;
                mask &= mask - 1;
                const bool has1 = (mask != 0);
                int n1 = n0;
                if (has1) { n1 = __ffs(mask) - 1; mask &= mask - 1; }

                const float4 pq0 = pqm[n0];           // broadcast LDS
                const float4 pq1 = pqm[n1];

                const float2 v0 = __ldg(reinterpret_cast<const float2*>(
                    features + (size_t)__float_as_int(pq0.w) * FD) + ln);
                const float2 v1 = __ldg(reinterpret_cast<const float2*>(
                    features + (size_t)__float_as_int(pq1.w) * FD) + ln);

                const float ex0 = pq0.x - kpx, ey0 = pq0.y - kpy, ez0 = pq0.z - kpz;
                const float w0 = 1.0f - __fsqrt_rn(ex0 * ex0 + ey0 * ey0 + ez0 * ez0);
                float w1 = 0.0f;
                if (has1) {
                    const float ex1 = pq1.x - kpx, ey1 = pq1.y - kpy, ez1 = pq1.z - kpz;
                    w1 = 1.0f - __fsqrt_rn(ex1 * ex1 + ey1 * ey1 + ez1 * ez1);
                }
                acc[mi][0] += w0 * v0.x + w1 * v1.x;
                acc[mi][1] += w0 * v0.y + w1 * v1.y;
            }
        }

        __syncthreads();   // all warps done with MMA(k-1): A/B buffers free

        // ---------- issue B(k) copy (k>0; B(0) pre-issued) ----------
        if (k > 0) {
            const char* srcH = reinterpret_cast<const char*>(g_Vt_hi) + (size_t)k * BTILE_BYTES;
            const char* srcL = reinterpret_cast<const char*>(g_Vt_lo) + (size_t)k * BTILE_BYTES;
            #pragma unroll
            for (int r = tid * 16; r < BTILE_BYTES; r += THREADS * 16) {
                cp16(smem_base + B_HI + r, srcH + r);
                cp16(smem_base + B_LO + r, srcL + r);
            }
            CP_COMMIT();
        }

        // ---------- convert + STS A tiles (lane ln -> bytes 4ln of row m) ----------
        #pragma unroll
        for (int mi = 0; mi < 8; ++mi) {
            const int m = wid * 8 + mi;
            const float a = acc[mi][0], b = acc[mi][1];
            __nv_bfloat162 hv;
            hv.x = __float2bfloat16_rn(a);
            hv.y = __float2bfloat16_rn(b);
            __nv_bfloat162 lv;
            lv.x = __float2bfloat16_rn(a - __bfloat162float(hv.x));
            lv.y = __float2bfloat16_rn(b - __bfloat162float(hv.y));
            *reinterpret_cast<uint32_t*>(smem + A_HI + m * ASTRIDE_B + ln * 4) =
                *reinterpret_cast<uint32_t*>(&hv);
            *reinterpret_cast<uint32_t*>(smem + A_LO + m * ASTRIDE_B + ln * 4) =
                *reinterpret_cast<uint32_t*>(&lv);
        }
        CP_WAIT0();
        __syncthreads();   // A/B(k) visible

        // ---------- mma: D += Ah·Bh + Ah·Bl + Al·Bh ----------
        #pragma unroll
        for (int ks = 0; ks < 4; ++ks) {
            uint32_t ah[4], al[4];
            ldmx4(ah, aaddr_hi + ks * 32);
            ldmx4(al, aaddr_lo + ks * 32);
            #pragma unroll
            for (int p = 0; p < 2; ++p) {
                uint32_t bh[4], bl[4];
                ldmx4(bh, baddr_hi + p * 16 * ASTRIDE_B + ks * 32);
                ldmx4(bl, baddr_lo + p * 16 * ASTRIDE_B + ks * 32);
                mma16816(Dacc[p * 2 + 0], ah, bh);
                mma16816(Dacc[p * 2 + 1], ah, bh + 2);
                mma16816(Dacc[p * 2 + 0], ah, bl);
                mma16816(Dacc[p * 2 + 1], ah, bl + 2);
                mma16816(Dacc[p * 2 + 0], al, bh);
                mma16816(Dacc[p * 2 + 1], al, bh + 2);
            }
        }
    }

    // ---------- epilogue ----------
    const int gid = ln >> 2, tg = ln & 3;
    const int r0 = m0 + wm + gid;
    const int r1 = r0 + 8;
    #pragma unroll
    for (int nt = 0; nt < 4; ++nt) {
        const int cc = wc + nt * 8 + tg * 2;
        if (r0 < Mpts)
            *reinterpret_cast<float2*>(out + (size_t)r0 * CD + cc) =
                make_float2(Dacc[nt][0], Dacc[nt][1]);
        if (r1 < Mpts)
            *reinterpret_cast<float2*>(out + (size_t)r1 * CD + cc) =
                make_float2(Dacc[nt][2], Dacc[nt][3]);
    }
}

extern "C" void kernel_launch(void* const* d_in, const int* in_sizes, int n_in,
                              void* d_out, int out_size)
{
    const float* points   = (const float*)d_in[0];
    const float* features = (const float*)d_in[1];
    const float* outpts   = (const float*)d_in[2];
    const int*   nbr      = (const int*)  d_in[3];
    const float* kpts     = (const float*)d_in[4];
    const float* kvals    = (const float*)d_in[5];

    vt_prep<<<(KP * 64 * 64 + 255) / 256, 256>>>(kvals);

    cudaFuncSetAttribute(kpconv_mma, cudaFuncAttributeMaxDynamicSharedMemorySize, SMEM_TOTAL);
    kpconv_mma<<<GRID, THREADS, SMEM_TOTAL>>>(points, features, outpts, nbr, kpts, (float*)d_out);
}

// round 6
// speedup vs baseline: 1.6896x; 1.6896x over previous
#include <cuda_runtime.h>
#include <cuda_bf16.h>
#include <cstdint>

#define Npts 100000
#define Mpts 100000
#define NNB 32
#define KP 15
#define FD 64
#define CD 64

constexpr int MT = 64;             // output points per block
constexpr int THREADS = 256;
constexpr int GRID = (Mpts + MT - 1) / MT;   // 1563

constexpr int ASTRIDE_B = 144;     // bytes per tile row (odd multiple of 16B -> conflict-free ldmatrix)
constexpr int ASTRIDE_E = 72;      // bf16 elems per row
constexpr int BTILE_BYTES = 64 * ASTRIDE_B;  // 9216

// ---- shared memory byte offsets ----
constexpr int A_HI = 0;            // [64][72] bf16 = 9216
constexpr int A_LO = 9216;
constexpr int B_HI = 18432;        // [64][72] bf16 = 9216
constexpr int B_LO = 27648;
constexpr int S_PQ = 36864;        // [64][32] float4 (dx,dy,dz, idx-bits) = 32768
constexpr int S_KM = 69632;        // [64][16] u32 per-(m,k) neighbor bitmask = 4096
constexpr int S_KP = 73728;        // [15][4] f32 = 240 -> 256
constexpr int SMEM_TOTAL = 73984;

// pre-transposed, padded B tiles: [k][c=64][f=72] bf16 (hi / lo split)
__device__ __align__(16) unsigned short g_Vt_hi[KP * 64 * ASTRIDE_E];
__device__ __align__(16) unsigned short g_Vt_lo[KP * 64 * ASTRIDE_E];

__device__ __forceinline__ uint32_t smem_u32(const void* p) {
    uint32_t a;
    asm("{ .reg .u64 t; cvta.to.shared.u64 t, %1; cvt.u32.u64 %0, t; }" : "=r"(a) : "l"(p));
    return a;
}

__device__ __forceinline__ void ldmx4(uint32_t* r, uint32_t addr) {
    asm volatile("ldmatrix.sync.aligned.m8n8.x4.shared.b16 {%0,%1,%2,%3}, [%4];"
                 : "=r"(r[0]), "=r"(r[1]), "=r"(r[2]), "=r"(r[3]) : "r"(addr));
}

__device__ __forceinline__ void mma16816(float* d, const uint32_t* a, const uint32_t* b) {
    asm volatile(
        "mma.sync.aligned.m16n8k16.row.col.f32.bf16.bf16.f32 "
        "{%0,%1,%2,%3}, {%4,%5,%6,%7}, {%8,%9}, {%0,%1,%2,%3};"
        : "+f"(d[0]), "+f"(d[1]), "+f"(d[2]), "+f"(d[3])
        : "r"(a[0]), "r"(a[1]), "r"(a[2]), "r"(a[3]), "r"(b[0]), "r"(b[1]));
}

__device__ __forceinline__ void cp16(uint32_t dst, const void* src) {
    asm volatile("cp.async.cg.shared.global [%0], [%1], 16;" :: "r"(dst), "l"(src));
}
#define CP_COMMIT() asm volatile("cp.async.commit_group;" ::: "memory")
#define CP_WAIT0()  asm volatile("cp.async.wait_group 0;" ::: "memory")

// ------------- prologue: transpose kvals [k][f][c] -> padded bf16 hi/lo [k][c][72] -------------
__global__ void vt_prep(const float* __restrict__ kv) {
    int id = blockIdx.x * blockDim.x + threadIdx.x;
    if (id >= KP * 64 * 64) return;
    int k = id >> 12;
    int rem = id & 4095;
    int f = rem >> 6;
    int c = rem & 63;
    float v = kv[id];
    __nv_bfloat16 hb = __float2bfloat16_rn(v);
    __nv_bfloat16 lb = __float2bfloat16_rn(v - __bfloat162float(hb));
    int dst = (k * 64 + c) * ASTRIDE_E + f;
    g_Vt_hi[dst] = __bfloat16_as_ushort(hb);
    g_Vt_lo[dst] = __bfloat16_as_ushort(lb);
}

// ------------------------------- main kernel -------------------------------
__global__ void __launch_bounds__(THREADS, 3)
kpconv_mma(const float* __restrict__ points,
           const float* __restrict__ features,
           const float* __restrict__ outpts,
           const int*   __restrict__ nbr,
           const float* __restrict__ kpts,
           float*       __restrict__ out)
{
    extern __shared__ char smem[];
    const uint32_t smem_base = smem_u32(smem);
    float*    s_kp = reinterpret_cast<float*>(smem + S_KP);
    unsigned* s_km = reinterpret_cast<unsigned*>(smem + S_KM);
    float4*   s_pq = reinterpret_cast<float4*>(smem + S_PQ);

    const int tid = threadIdx.x;
    const int wid = tid >> 5;
    const int ln  = tid & 31;
    const int m0  = blockIdx.x * MT;

    if (tid < KP * 3) s_kp[(tid / 3) * 4 + (tid % 3)] = kpts[tid];
    __syncthreads();

    // ---- setup: pq vectors + per-(m,k) neighbor bitmasks ----
    #pragma unroll 1
    for (int j = 0; j < (MT * NNB) / THREADS; ++j) {
        const int i = j * THREADS + tid;
        const int m = i >> 5;                 // constant within a warp
        const int gm = m0 + m;
        float dx, dy, dz;
        int gi = 0;
        if (gm < Mpts) {
            gi = nbr[(size_t)gm * NNB + ln];
            const float qx = outpts[gm * 3 + 0];
            const float qy = outpts[gm * 3 + 1];
            const float qz = outpts[gm * 3 + 2];
            dx = __ldg(points + 3 * (size_t)gi + 0) - qx;
            dy = __ldg(points + 3 * (size_t)gi + 1) - qy;
            dz = __ldg(points + 3 * (size_t)gi + 2) - qz;
        } else {
            dx = dy = dz = 1e18f;
        }
        s_pq[i] = make_float4(dx, dy, dz, __int_as_float(gi));
        #pragma unroll
        for (int k = 0; k < KP; ++k) {
            const float ex = dx - s_kp[k * 4 + 0];
            const float ey = dy - s_kp[k * 4 + 1];
            const float ez = dz - s_kp[k * 4 + 2];
            const float d2 = ex * ex + ey * ey + ez * ez;
            const unsigned bal = __ballot_sync(0xffffffffu, d2 < 1.0f);
            if (ln == 0) s_km[m * 16 + k] = bal;
        }
    }

    // ---- per-thread mappings ----
    const int mgrp = tid >> 3;          // gather: 8 threads per m, 32 m's per pass
    const int oct  = tid & 7;           // 16B chunk index: oct and oct+8

    const int wm = (wid & 3) * 16;      // mma warp tile: rows
    const int wc = (wid >> 2) * 32;     // mma warp tile: cols
    const int arow = wm + (ln & 7) + ((ln >> 3) & 1) * 8;
    const uint32_t aoff = (uint32_t)(arow * ASTRIDE_B + ((ln >> 4) & 1) * 16);
    const uint32_t aaddr_hi = smem_base + A_HI + aoff;
    const uint32_t aaddr_lo = smem_base + A_LO + aoff;
    const int brow = wc + (ln & 7) + ((ln >> 4) & 1) * 8;
    const uint32_t boff = (uint32_t)(brow * ASTRIDE_B + ((ln >> 3) & 1) * 16);
    const uint32_t baddr_hi = smem_base + B_HI + boff;
    const uint32_t baddr_lo = smem_base + B_LO + boff;

    float Dacc[4][4];
    #pragma unroll
    for (int a = 0; a < 4; ++a)
        #pragma unroll
        for (int b = 0; b < 4; ++b) Dacc[a][b] = 0.f;

    __syncthreads();   // masks + pq visible

    // ---- pre-issue B(0) copy (overlaps with gather(0)) ----
    {
        const char* srcH = reinterpret_cast<const char*>(g_Vt_hi);
        const char* srcL = reinterpret_cast<const char*>(g_Vt_lo);
        #pragma unroll
        for (int r = tid * 16; r < BTILE_BYTES; r += THREADS * 16) {
            cp16(smem_base + B_HI + r, srcH + r);
            cp16(smem_base + B_LO + r, srcL + r);
        }
        CP_COMMIT();
    }

    #pragma unroll 1
    for (int k = 0; k < KP; ++k) {
        const float kpx = s_kp[k * 4 + 0];
        const float kpy = s_kp[k * 4 + 1];
        const float kpz = s_kp[k * 4 + 2];

        // ---------- gather wf_k: 8 threads/m, fully coalesced rows ----------
        // thread (mgrp, oct) accumulates features [4*oct..4*oct+3] and
        // [32+4*oct..35+4*oct] of m = pass*32 + mgrp. Each LDG.128 covers a
        // full 128B line across the 8 octs -> 2 wavefronts per 256B row.
        float acc[2][8];
        #pragma unroll
        for (int p = 0; p < 2; ++p)
            #pragma unroll
            for (int i = 0; i < 8; ++i) acc[p][i] = 0.f;

        #pragma unroll
        for (int p = 0; p < 2; ++p) {
            const int m = p * 32 + mgrp;
            unsigned mask = s_km[m * 16 + k];
            const float4* pqm = s_pq + m * 32;
            while (mask) {
                const int n0 = __ffs(mask) - 1;
                mask &= mask - 1;
                const bool has1 = (mask != 0);
                int n1 = n0;
                if (has1) { n1 = __ffs(mask) - 1; mask &= mask - 1; }

                const float4 pq0 = pqm[n0];       // broadcast LDS across octs
                const float4 pq1 = pqm[n1];

                const float4* fp0 = reinterpret_cast<const float4*>(
                    features + (size_t)__float_as_int(pq0.w) * FD);
                const float4* fp1 = reinterpret_cast<const float4*>(
                    features + (size_t)__float_as_int(pq1.w) * FD);
                const float4 a0 = __ldg(fp0 + oct);
                const float4 b0 = __ldg(fp0 + oct + 8);
                const float4 a1 = __ldg(fp1 + oct);
                const float4 b1 = __ldg(fp1 + oct + 8);

                const float ex0 = pq0.x - kpx, ey0 = pq0.y - kpy, ez0 = pq0.z - kpz;
                const float w0 = 1.0f - __fsqrt_rn(ex0 * ex0 + ey0 * ey0 + ez0 * ez0);
                float w1 = 0.0f;
                if (has1) {
                    const float ex1 = pq1.x - kpx, ey1 = pq1.y - kpy, ez1 = pq1.z - kpz;
                    w1 = 1.0f - __fsqrt_rn(ex1 * ex1 + ey1 * ey1 + ez1 * ez1);
                }
                acc[p][0] += w0 * a0.x + w1 * a1.x;
                acc[p][1] += w0 * a0.y + w1 * a1.y;
                acc[p][2] += w0 * a0.z + w1 * a1.z;
                acc[p][3] += w0 * a0.w + w1 * a1.w;
                acc[p][4] += w0 * b0.x + w1 * b1.x;
                acc[p][5] += w0 * b0.y + w1 * b1.y;
                acc[p][6] += w0 * b0.z + w1 * b1.z;
                acc[p][7] += w0 * b0.w + w1 * b1.w;
            }
        }

        __syncthreads();   // all warps done with MMA(k-1): A/B buffers free

        // ---------- issue B(k) copy (k>0; B(0) pre-issued) ----------
        if (k > 0) {
            const char* srcH = reinterpret_cast<const char*>(g_Vt_hi) + (size_t)k * BTILE_BYTES;
            const char* srcL = reinterpret_cast<const char*>(g_Vt_lo) + (size_t)k * BTILE_BYTES;
            #pragma unroll
            for (int r = tid * 16; r < BTILE_BYTES; r += THREADS * 16) {
                cp16(smem_base + B_HI + r, srcH + r);
                cp16(smem_base + B_LO + r, srcL + r);
            }
            CP_COMMIT();
        }

        // ---------- convert + STS A tiles ----------
        // features 4*oct.. -> bytes 8*oct ; features 32+4*oct.. -> bytes 64+8*oct
        #pragma unroll
        for (int p = 0; p < 2; ++p) {
            const int m = p * 32 + mgrp;
            uint32_t hw[4], lw[4];
            #pragma unroll
            for (int i = 0; i < 4; ++i) {
                const float a = acc[p][2 * i], b = acc[p][2 * i + 1];
                __nv_bfloat162 hv;
                hv.x = __float2bfloat16_rn(a);
                hv.y = __float2bfloat16_rn(b);
                __nv_bfloat162 lv;
                lv.x = __float2bfloat16_rn(a - __bfloat162float(hv.x));
                lv.y = __float2bfloat16_rn(b - __bfloat162float(hv.y));
                hw[i] = *reinterpret_cast<uint32_t*>(&hv);
                lw[i] = *reinterpret_cast<uint32_t*>(&lv);
            }
            const uint32_t base = (uint32_t)(m * ASTRIDE_B + oct * 8);
            *reinterpret_cast<uint2*>(smem + A_HI + base)      = make_uint2(hw[0], hw[1]);
            *reinterpret_cast<uint2*>(smem + A_HI + base + 64) = make_uint2(hw[2], hw[3]);
            *reinterpret_cast<uint2*>(smem + A_LO + base)      = make_uint2(lw[0], lw[1]);
            *reinterpret_cast<uint2*>(smem + A_LO + base + 64) = make_uint2(lw[2], lw[3]);
        }
        CP_WAIT0();
        __syncthreads();   // A/B(k) visible

        // ---------- mma: D += Ah·Bh + Ah·Bl + Al·Bh ----------
        #pragma unroll
        for (int ks = 0; ks < 4; ++ks) {
            uint32_t ah[4], al[4];
            ldmx4(ah, aaddr_hi + ks * 32);
            ldmx4(al, aaddr_lo + ks * 32);
            #pragma unroll
            for (int p = 0; p < 2; ++p) {
                uint32_t bh[4], bl[4];
                ldmx4(bh, baddr_hi + p * 16 * ASTRIDE_B + ks * 32);
                ldmx4(bl, baddr_lo + p * 16 * ASTRIDE_B + ks * 32);
                mma16816(Dacc[p * 2 + 0], ah, bh);
                mma16816(Dacc[p * 2 + 1], ah, bh + 2);
                mma16816(Dacc[p * 2 + 0], ah, bl);
                mma16816(Dacc[p * 2 + 1], ah, bl + 2);
                mma16816(Dacc[p * 2 + 0], al, bh);
                mma16816(Dacc[p * 2 + 1], al, bh + 2);
            }
        }
    }

    // ---------- epilogue ----------
    const int gid = ln >> 2, tg = ln & 3;
    const int r0 = m0 + wm + gid;
    const int r1 = r0 + 8;
    #pragma unroll
    for (int nt = 0; nt < 4; ++nt) {
        const int cc = wc + nt * 8 + tg * 2;
        if (r0 < Mpts)
            *reinterpret_cast<float2*>(out + (size_t)r0 * CD + cc) =
                make_float2(Dacc[nt][0], Dacc[nt][1]);
        if (r1 < Mpts)
            *reinterpret_cast<float2*>(out + (size_t)r1 * CD + cc) =
                make_float2(Dacc[nt][2], Dacc[nt][3]);
    }
}

extern "C" void kernel_launch(void* const* d_in, const int* in_sizes, int n_in,
                              void* d_out, int out_size)
{
    const float* points   = (const float*)d_in[0];
    const float* features = (const float*)d_in[1];
    const float* outpts   = (const float*)d_in[2];
    const int*   nbr      = (const int*)  d_in[3];
    const float* kpts     = (const float*)d_in[4];
    const float* kvals    = (const float*)d_in[5];

    vt_prep<<<(KP * 64 * 64 + 255) / 256, 256>>>(kvals);

    cudaFuncSetAttribute(kpconv_mma, cudaFuncAttributeMaxDynamicSharedMemorySize, SMEM_TOTAL);
    kpconv_mma<<<GRID, THREADS, SMEM_TOTAL>>>(points, features, outpts, nbr, kpts, (float*)d_out);
}

// round 7
// speedup vs baseline: 1.7433x; 1.0318x over previous
#include <cuda_runtime.h>
#include <cstdint>

#define Npts 100000
#define Mpts 100000
#define NNB 32
#define KP 15
#define FD 64
#define CD 64

constexpr int MT = 64;             // output points per block
constexpr int THREADS = 256;
constexpr int GRID = (Mpts + MT - 1) / MT;   // 1563

constexpr int TSTR_F = 68;         // tile row stride in floats (272B; 272%128=16 -> ldmatrix conflict-free)
constexpr int TSTR_B = 272;
constexpr int BTILE_BYTES = 64 * TSTR_B;     // 17408

// ---- shared memory byte offsets ----
constexpr int A_T  = 0;            // [64 m][68] f32 = 17408
constexpr int B_T  = 17408;        // [64 c][68] f32 = 17408
constexpr int S_PQ = 34816;        // [64][32] float4 (dx,dy,dz, idx-bits) = 32768
constexpr int S_KM = 67584;        // [64][16] u32 per-(m,k) neighbor bitmask = 4096
constexpr int S_KP = 71680;        // [15][4] f32 = 256
constexpr int SMEM_TOTAL = 71936;

// pre-transposed, tf32-rounded B tiles: [k][c=64][68] f32
__device__ __align__(16) uint32_t g_Vt[KP * 64 * TSTR_F];

__device__ __forceinline__ uint32_t smem_u32(const void* p) {
    uint32_t a;
    asm("{ .reg .u64 t; cvta.to.shared.u64 t, %1; cvt.u32.u64 %0, t; }" : "=r"(a) : "l"(p));
    return a;
}

__device__ __forceinline__ void ldmx4(uint32_t* r, uint32_t addr) {
    asm volatile("ldmatrix.sync.aligned.m8n8.x4.shared.b16 {%0,%1,%2,%3}, [%4];"
                 : "=r"(r[0]), "=r"(r[1]), "=r"(r[2]), "=r"(r[3]) : "r"(addr));
}

__device__ __forceinline__ void mma1688(float* d, const uint32_t* a, const uint32_t* b) {
    asm volatile(
        "mma.sync.aligned.m16n8k8.row.col.f32.tf32.tf32.f32 "
        "{%0,%1,%2,%3}, {%4,%5,%6,%7}, {%8,%9}, {%0,%1,%2,%3};"
        : "+f"(d[0]), "+f"(d[1]), "+f"(d[2]), "+f"(d[3])
        : "r"(a[0]), "r"(a[1]), "r"(a[2]), "r"(a[3]), "r"(b[0]), "r"(b[1]));
}

__device__ __forceinline__ uint32_t tf32r(float x) {
    uint32_t u;
    asm("cvt.rna.tf32.f32 %0, %1;" : "=r"(u) : "f"(x));
    return u;
}

__device__ __forceinline__ void cp16(uint32_t dst, const void* src) {
    asm volatile("cp.async.cg.shared.global [%0], [%1], 16;" :: "r"(dst), "l"(src));
}
#define CP_COMMIT() asm volatile("cp.async.commit_group;" ::: "memory")
#define CP_WAIT0()  asm volatile("cp.async.wait_group 0;" ::: "memory")

// ------------- prologue: transpose kvals [k][f][c] -> tf32-rounded [k][c][68] -------------
__global__ void vt_prep(const float* __restrict__ kv) {
    int id = blockIdx.x * blockDim.x + threadIdx.x;
    if (id >= KP * 64 * 64) return;
    int k = id >> 12;
    int rem = id & 4095;
    int f = rem >> 6;
    int c = rem & 63;
    g_Vt[(k * 64 + c) * TSTR_F + f] = tf32r(kv[id]);
}

// ------------------------------- main kernel -------------------------------
__global__ void __launch_bounds__(THREADS, 3)
kpconv_mma(const float* __restrict__ points,
           const float* __restrict__ features,
           const float* __restrict__ outpts,
           const int*   __restrict__ nbr,
           const float* __restrict__ kpts,
           float*       __restrict__ out)
{
    extern __shared__ char smem[];
    const uint32_t smem_base = smem_u32(smem);
    float*    s_kp = reinterpret_cast<float*>(smem + S_KP);
    unsigned* s_km = reinterpret_cast<unsigned*>(smem + S_KM);
    float4*   s_pq = reinterpret_cast<float4*>(smem + S_PQ);

    const int tid = threadIdx.x;
    const int wid = tid >> 5;
    const int ln  = tid & 31;
    const int m0  = blockIdx.x * MT;

    if (tid < KP * 3) s_kp[(tid / 3) * 4 + (tid % 3)] = kpts[tid];
    __syncthreads();

    // ---- setup: pq vectors + per-(m,k) neighbor bitmasks ----
    #pragma unroll 1
    for (int j = 0; j < (MT * NNB) / THREADS; ++j) {
        const int i = j * THREADS + tid;
        const int m = i >> 5;                 // constant within a warp
        const int gm = m0 + m;
        float dx, dy, dz;
        int gi = 0;
        if (gm < Mpts) {
            gi = nbr[(size_t)gm * NNB + ln];
            const float qx = outpts[gm * 3 + 0];
            const float qy = outpts[gm * 3 + 1];
            const float qz = outpts[gm * 3 + 2];
            dx = __ldg(points + 3 * (size_t)gi + 0) - qx;
            dy = __ldg(points + 3 * (size_t)gi + 1) - qy;
            dz = __ldg(points + 3 * (size_t)gi + 2) - qz;
        } else {
            dx = dy = dz = 1e18f;
        }
        s_pq[i] = make_float4(dx, dy, dz, __int_as_float(gi));
        #pragma unroll
        for (int k = 0; k < KP; ++k) {
            const float ex = dx - s_kp[k * 4 + 0];
            const float ey = dy - s_kp[k * 4 + 1];
            const float ez = dz - s_kp[k * 4 + 2];
            const float d2 = ex * ex + ey * ey + ez * ez;
            const unsigned bal = __ballot_sync(0xffffffffu, d2 < 1.0f);
            if (ln == 0) s_km[m * 16 + k] = bal;
        }
    }

    // ---- per-thread mappings ----
    const int mgrp = tid >> 3;          // gather: 8 threads per m, 32 m's per pass
    const int oct  = tid & 7;           // 16B chunk index: oct and oct+8

    const int wm = (wid & 3) * 16;      // mma warp tile: rows
    const int wc = (wid >> 2) * 32;     // mma warp tile: cols
    // ldmatrix-x4-on-fp32 addressing (b16 matrices = 8 rows x 4 f32)
    const uint32_t aaddr = smem_base + A_T +
        (uint32_t)((wm + (ln & 7) + ((ln >> 3) & 1) * 8) * TSTR_B + ((ln >> 4) & 1) * 16);
    const uint32_t baddr = smem_base + B_T +
        (uint32_t)((wc + (ln & 7) + ((ln >> 4) & 1) * 8) * TSTR_B + ((ln >> 3) & 1) * 16);

    float Dacc[4][4];
    #pragma unroll
    for (int a = 0; a < 4; ++a)
        #pragma unroll
        for (int b = 0; b < 4; ++b) Dacc[a][b] = 0.f;

    __syncthreads();   // masks + pq visible

    // ---- pre-issue B(0) copy (overlaps with gather(0)) ----
    {
        const char* src = reinterpret_cast<const char*>(g_Vt);
        #pragma unroll
        for (int r = tid * 16; r < BTILE_BYTES; r += THREADS * 16)
            cp16(smem_base + B_T + r, src + r);
        CP_COMMIT();
    }

    #pragma unroll 1
    for (int k = 0; k < KP; ++k) {
        const float kpx = s_kp[k * 4 + 0];
        const float kpy = s_kp[k * 4 + 1];
        const float kpz = s_kp[k * 4 + 2];

        // ---------- gather wf_k: 8 threads/m, fully coalesced rows ----------
        float acc[2][8];
        #pragma unroll
        for (int p = 0; p < 2; ++p)
            #pragma unroll
            for (int i = 0; i < 8; ++i) acc[p][i] = 0.f;

        #pragma unroll
        for (int p = 0; p < 2; ++p) {
            const int m = p * 32 + mgrp;
            unsigned mask = s_km[m * 16 + k];
            const float4* pqm = s_pq + m * 32;
            while (mask) {
                const int n0 = __ffs(mask) - 1;
                mask &= mask - 1;
                const bool has1 = (mask != 0);
                int n1 = n0;
                if (has1) { n1 = __ffs(mask) - 1; mask &= mask - 1; }

                const float4 pq0 = pqm[n0];       // broadcast LDS across octs
                const float4 pq1 = pqm[n1];

                const float4* fp0 = reinterpret_cast<const float4*>(
                    features + (size_t)__float_as_int(pq0.w) * FD);
                const float4* fp1 = reinterpret_cast<const float4*>(
                    features + (size_t)__float_as_int(pq1.w) * FD);
                const float4 a0 = __ldg(fp0 + oct);
                const float4 b0 = __ldg(fp0 + oct + 8);
                const float4 a1 = __ldg(fp1 + oct);
                const float4 b1 = __ldg(fp1 + oct + 8);

                const float ex0 = pq0.x - kpx, ey0 = pq0.y - kpy, ez0 = pq0.z - kpz;
                const float w0 = 1.0f - __fsqrt_rn(ex0 * ex0 + ey0 * ey0 + ez0 * ez0);
                float w1 = 0.0f;
                if (has1) {
                    const float ex1 = pq1.x - kpx, ey1 = pq1.y - kpy, ez1 = pq1.z - kpz;
                    w1 = 1.0f - __fsqrt_rn(ex1 * ex1 + ey1 * ey1 + ez1 * ez1);
                }
                acc[p][0] += w0 * a0.x + w1 * a1.x;
                acc[p][1] += w0 * a0.y + w1 * a1.y;
                acc[p][2] += w0 * a0.z + w1 * a1.z;
                acc[p][3] += w0 * a0.w + w1 * a1.w;
                acc[p][4] += w0 * b0.x + w1 * b1.x;
                acc[p][5] += w0 * b0.y + w1 * b1.y;
                acc[p][6] += w0 * b0.z + w1 * b1.z;
                acc[p][7] += w0 * b0.w + w1 * b1.w;
            }
        }

        __syncthreads();   // all warps done with MMA(k-1): A/B buffers free

        // ---------- issue B(k) copy (k>0; B(0) pre-issued) ----------
        if (k > 0) {
            const char* src = reinterpret_cast<const char*>(g_Vt) + (size_t)k * BTILE_BYTES;
            #pragma unroll
            for (int r = tid * 16; r < BTILE_BYTES; r += THREADS * 16)
                cp16(smem_base + B_T + r, src + r);
            CP_COMMIT();
        }

        // ---------- tf32-round + STS A tile (fp32) ----------
        #pragma unroll
        for (int p = 0; p < 2; ++p) {
            const int m = p * 32 + mgrp;
            uint32_t t[8];
            #pragma unroll
            for (int i = 0; i < 8; ++i) t[i] = tf32r(acc[p][i]);
            const uint32_t base = (uint32_t)(m * TSTR_B + oct * 16);
            *reinterpret_cast<uint4*>(smem + A_T + base)       = make_uint4(t[0], t[1], t[2], t[3]);
            *reinterpret_cast<uint4*>(smem + A_T + base + 128) = make_uint4(t[4], t[5], t[6], t[7]);
        }
        CP_WAIT0();
        __syncthreads();   // A/B(k) visible

        // ---------- mma: D += A · B  (tf32, single product) ----------
        #pragma unroll
        for (int ks = 0; ks < 8; ++ks) {
            uint32_t a[4];
            ldmx4(a, aaddr + ks * 32);
            #pragma unroll
            for (int nt2 = 0; nt2 < 2; ++nt2) {
                uint32_t b[4];
                ldmx4(b, baddr + nt2 * (16 * TSTR_B) + ks * 32);
                mma1688(Dacc[nt2 * 2 + 0], a, b);
                mma1688(Dacc[nt2 * 2 + 1], a, b + 2);
            }
        }
    }

    // ---------- epilogue ----------
    const int gid = ln >> 2, tg = ln & 3;
    const int r0 = m0 + wm + gid;
    const int r1 = r0 + 8;
    #pragma unroll
    for (int nt = 0; nt < 4; ++nt) {
        const int cc = wc + nt * 8 + tg * 2;
        if (r0 < Mpts)
            *reinterpret_cast<float2*>(out + (size_t)r0 * CD + cc) =
                make_float2(Dacc[nt][0], Dacc[nt][1]);
        if (r1 < Mpts)
            *reinterpret_cast<float2*>(out + (size_t)r1 * CD + cc) =
                make_float2(Dacc[nt][2], Dacc[nt][3]);
    }
}

extern "C" void kernel_launch(void* const* d_in, const int* in_sizes, int n_in,
                              void* d_out, int out_size)
{
    const float* points   = (const float*)d_in[0];
    const float* features = (const float*)d_in[1];
    const float* outpts   = (const float*)d_in[2];
    const int*   nbr      = (const int*)  d_in[3];
    const float* kpts     = (const float*)d_in[4];
    const float* kvals    = (const float*)d_in[5];

    vt_prep<<<(KP * 64 * 64 + 255) / 256, 256>>>(kvals);

    cudaFuncSetAttribute(kpconv_mma, cudaFuncAttributeMaxDynamicSharedMemorySize, SMEM_TOTAL);
    kpconv_mma<<<GRID, THREADS, SMEM_TOTAL>>>(points, features, outpts, nbr, kpts, (float*)d_out);
}

// round 8
// speedup vs baseline: 1.8686x; 1.0718x over previous
#include <cuda_runtime.h>
#include <cstdint>

#define Npts 100000
#define Mpts 100000
#define NNB 32
#define KP 15
#define FD 64
#define CD 64

constexpr int MT = 64;             // output points per block
constexpr int THREADS = 256;
constexpr int GRID = (Mpts + MT - 1) / MT;   // 1563

constexpr int TSTR_F = 68;         // tile row stride in floats (272B; 272%128=16 -> ldmatrix conflict-free)
constexpr int TSTR_B = 272;
constexpr int ATILE_BYTES = 64 * TSTR_B;     // 17408

// ---- shared memory byte offsets ----
constexpr int A_T0 = 0;            // [64 m][68] f32 (buffer 0)
constexpr int A_T1 = 17408;        // buffer 1
constexpr int S_PQ = 34816;        // [64][32] float4 (dx,dy,dz, idx-bits) = 32768
constexpr int S_KM = 67584;        // [64][16] u32 per-(m,k) neighbor bitmask = 4096
constexpr int S_KP = 71680;        // [15][4] f32 = 256
constexpr int SMEM_TOTAL = 71936;

// B fragments in mma register layout: [k][wc(2)][ks(8)][nt2(2)][lane(32)] uint4
__device__ __align__(16) uint4 g_Bfrag[KP * 2 * 8 * 2 * 32];

__device__ __forceinline__ uint32_t smem_u32(const void* p) {
    uint32_t a;
    asm("{ .reg .u64 t; cvta.to.shared.u64 t, %1; cvt.u32.u64 %0, t; }" : "=r"(a) : "l"(p));
    return a;
}

__device__ __forceinline__ void ldmx4(uint32_t* r, uint32_t addr) {
    asm volatile("ldmatrix.sync.aligned.m8n8.x4.shared.b16 {%0,%1,%2,%3}, [%4];"
                 : "=r"(r[0]), "=r"(r[1]), "=r"(r[2]), "=r"(r[3]) : "r"(addr));
}

__device__ __forceinline__ void mma1688(float* d, const uint32_t* a, uint32_t b0, uint32_t b1) {
    asm volatile(
        "mma.sync.aligned.m16n8k8.row.col.f32.tf32.tf32.f32 "
        "{%0,%1,%2,%3}, {%4,%5,%6,%7}, {%8,%9}, {%0,%1,%2,%3};"
        : "+f"(d[0]), "+f"(d[1]), "+f"(d[2]), "+f"(d[3])
        : "r"(a[0]), "r"(a[1]), "r"(a[2]), "r"(a[3]), "r"(b0), "r"(b1));
}

__device__ __forceinline__ uint32_t tf32r(float x) {
    uint32_t u;
    asm("cvt.rna.tf32.f32 %0, %1;" : "=r"(u) : "f"(x));
    return u;
}

// ------------- prologue: build B fragments in exact mma register layout -------------
// one block per kernel point; 2 warps, warp w handles wc = w*32.
__global__ void bfrag_prep(const float* __restrict__ kv) {
    __shared__ __align__(16) uint32_t tile[64 * TSTR_F];
    const int k   = blockIdx.x;
    const int tid = threadIdx.x;
    const int wid = tid >> 5;
    const int ln  = tid & 31;

    // stage tile[c][f] = tf32(kv[k][f][c])
    for (int j = 0; j < 64; ++j) {
        const int f = j, c = tid;
        tile[c * TSTR_F + f] = tf32r(kv[((size_t)k * 64 + f) * 64 + c]);
    }
    __syncthreads();

    const int wc = wid * 32;
    const uint32_t base = smem_u32(tile) +
        (uint32_t)((wc + (ln & 7) + ((ln >> 4) & 1) * 8) * TSTR_B + ((ln >> 3) & 1) * 16);
    #pragma unroll
    for (int ks = 0; ks < 8; ++ks) {
        #pragma unroll
        for (int nt2 = 0; nt2 < 2; ++nt2) {
            uint32_t b[4];
            ldmx4(b, base + nt2 * (16 * TSTR_B) + ks * 32);
            g_Bfrag[(((k * 2 + wid) * 8 + ks) * 2 + nt2) * 32 + ln] =
                make_uint4(b[0], b[1], b[2], b[3]);
        }
    }
}

// ------------------------------- main kernel -------------------------------
__global__ void __launch_bounds__(THREADS, 3)
kpconv_mma(const float* __restrict__ points,
           const float* __restrict__ features,
           const float* __restrict__ outpts,
           const int*   __restrict__ nbr,
           const float* __restrict__ kpts,
           float*       __restrict__ out)
{
    extern __shared__ char smem[];
    const uint32_t smem_base = smem_u32(smem);
    float*    s_kp = reinterpret_cast<float*>(smem + S_KP);
    unsigned* s_km = reinterpret_cast<unsigned*>(smem + S_KM);
    float4*   s_pq = reinterpret_cast<float4*>(smem + S_PQ);

    const int tid = threadIdx.x;
    const int wid = tid >> 5;
    const int ln  = tid & 31;
    const int m0  = blockIdx.x * MT;

    if (tid < KP * 3) s_kp[(tid / 3) * 4 + (tid % 3)] = kpts[tid];
    __syncthreads();

    // ---- setup: pq vectors + per-(m,k) neighbor bitmasks ----
    #pragma unroll 1
    for (int j = 0; j < (MT * NNB) / THREADS; ++j) {
        const int i = j * THREADS + tid;
        const int m = i >> 5;                 // constant within a warp
        const int gm = m0 + m;
        float dx, dy, dz;
        int gi = 0;
        if (gm < Mpts) {
            gi = nbr[(size_t)gm * NNB + ln];
            const float qx = outpts[gm * 3 + 0];
            const float qy = outpts[gm * 3 + 1];
            const float qz = outpts[gm * 3 + 2];
            dx = __ldg(points + 3 * (size_t)gi + 0) - qx;
            dy = __ldg(points + 3 * (size_t)gi + 1) - qy;
            dz = __ldg(points + 3 * (size_t)gi + 2) - qz;
        } else {
            dx = dy = dz = 1e18f;
        }
        s_pq[i] = make_float4(dx, dy, dz, __int_as_float(gi));
        #pragma unroll
        for (int k = 0; k < KP; ++k) {
            const float ex = dx - s_kp[k * 4 + 0];
            const float ey = dy - s_kp[k * 4 + 1];
            const float ez = dz - s_kp[k * 4 + 2];
            const float d2 = ex * ex + ey * ey + ez * ez;
            const unsigned bal = __ballot_sync(0xffffffffu, d2 < 1.0f);
            if (ln == 0) s_km[m * 16 + k] = bal;
        }
    }

    // ---- per-thread mappings ----
    const int mgrp = tid >> 3;          // gather: 8 threads per m, 32 m's per pass
    const int oct  = tid & 7;           // 16B chunk index: oct and oct+8

    const int wm = (wid & 3) * 16;      // mma warp tile: rows
    const int wc = (wid >> 2) * 32;     // mma warp tile: cols
    // ldmatrix-x4-on-fp32 addressing for A (b16 matrices = 8 rows x 4 f32)
    const uint32_t aaddr = smem_base + A_T0 +
        (uint32_t)((wm + (ln & 7) + ((ln >> 3) & 1) * 8) * TSTR_B + ((ln >> 4) & 1) * 16);
    // B fragment pointer for this warp's column half
    const uint4* bwarp = g_Bfrag + ((wid >> 2) * 8 * 2) * 32 + ln;

    float Dacc[4][4];
    #pragma unroll
    for (int a = 0; a < 4; ++a)
        #pragma unroll
        for (int b = 0; b < 4; ++b) Dacc[a][b] = 0.f;

    __syncthreads();   // masks + pq visible

    #pragma unroll 1
    for (int k = 0; k < KP; ++k) {
        const float kpx = s_kp[k * 4 + 0];
        const float kpy = s_kp[k * 4 + 1];
        const float kpz = s_kp[k * 4 + 2];

        // ---------- gather wf_k: 8 threads/m, fully coalesced rows ----------
        float acc[2][8];
        #pragma unroll
        for (int p = 0; p < 2; ++p)
            #pragma unroll
            for (int i = 0; i < 8; ++i) acc[p][i] = 0.f;

        #pragma unroll
        for (int p = 0; p < 2; ++p) {
            const int m = p * 32 + mgrp;
            unsigned mask = s_km[m * 16 + k];
            const float4* pqm = s_pq + m * 32;
            while (mask) {
                const int n0 = __ffs(mask) - 1;
                mask &= mask - 1;
                const bool has1 = (mask != 0);
                int n1 = n0;
                if (has1) { n1 = __ffs(mask) - 1; mask &= mask - 1; }

                const float4 pq0 = pqm[n0];       // broadcast LDS across octs
                const float4 pq1 = pqm[n1];

                const float4* fp0 = reinterpret_cast<const float4*>(
                    features + (size_t)__float_as_int(pq0.w) * FD);
                const float4* fp1 = reinterpret_cast<const float4*>(
                    features + (size_t)__float_as_int(pq1.w) * FD);
                const float4 a0 = __ldg(fp0 + oct);
                const float4 b0 = __ldg(fp0 + oct + 8);
                const float4 a1 = __ldg(fp1 + oct);
                const float4 b1 = __ldg(fp1 + oct + 8);

                const float ex0 = pq0.x - kpx, ey0 = pq0.y - kpy, ez0 = pq0.z - kpz;
                const float w0 = 1.0f - __fsqrt_rn(ex0 * ex0 + ey0 * ey0 + ez0 * ez0);
                float w1 = 0.0f;
                if (has1) {
                    const float ex1 = pq1.x - kpx, ey1 = pq1.y - kpy, ez1 = pq1.z - kpz;
                    w1 = 1.0f - __fsqrt_rn(ex1 * ex1 + ey1 * ey1 + ez1 * ez1);
                }
                acc[p][0] += w0 * a0.x + w1 * a1.x;
                acc[p][1] += w0 * a0.y + w1 * a1.y;
                acc[p][2] += w0 * a0.z + w1 * a1.z;
                acc[p][3] += w0 * a0.w + w1 * a1.w;
                acc[p][4] += w0 * b0.x + w1 * b1.x;
                acc[p][5] += w0 * b0.y + w1 * b1.y;
                acc[p][6] += w0 * b0.z + w1 * b1.z;
                acc[p][7] += w0 * b0.w + w1 * b1.w;
            }
        }

        // ---------- tf32-round + STS A tile into parity buffer ----------
        const uint32_t abase = (uint32_t)((k & 1) * ATILE_BYTES);
        #pragma unroll
        for (int p = 0; p < 2; ++p) {
            const int m = p * 32 + mgrp;
            uint32_t t[8];
            #pragma unroll
            for (int i = 0; i < 8; ++i) t[i] = tf32r(acc[p][i]);
            const uint32_t base = abase + (uint32_t)(m * TSTR_B + oct * 16);
            *reinterpret_cast<uint4*>(smem + base)       = make_uint4(t[0], t[1], t[2], t[3]);
            *reinterpret_cast<uint4*>(smem + base + 128) = make_uint4(t[4], t[5], t[6], t[7]);
        }
        __syncthreads();   // A(k) visible; MMA(k-1) ldmatrix already issued by all warps

        // ---------- mma: D += A · B  (tf32; B operands via coalesced LDG) ----------
        const uint4* bk = bwarp + (size_t)k * (2 * 8 * 2 * 32);
        const uint32_t abuf = aaddr + abase;
        #pragma unroll
        for (int ks = 0; ks < 8; ++ks) {
            uint32_t a[4];
            ldmx4(a, abuf + ks * 32);
            #pragma unroll
            for (int nt2 = 0; nt2 < 2; ++nt2) {
                const uint4 bb = __ldg(bk + (ks * 2 + nt2) * 32);
                mma1688(Dacc[nt2 * 2 + 0], a, bb.x, bb.y);
                mma1688(Dacc[nt2 * 2 + 1], a, bb.z, bb.w);
            }
        }
    }

    // ---------- epilogue ----------
    const int gid = ln >> 2, tg = ln & 3;
    const int r0 = m0 + wm + gid;
    const int r1 = r0 + 8;
    #pragma unroll
    for (int nt = 0; nt < 4; ++nt) {
        const int cc = wc + nt * 8 + tg * 2;
        if (r0 < Mpts)
            *reinterpret_cast<float2*>(out + (size_t)r0 * CD + cc) =
                make_float2(Dacc[nt][0], Dacc[nt][1]);
        if (r1 < Mpts)
            *reinterpret_cast<float2*>(out + (size_t)r1 * CD + cc) =
                make_float2(Dacc[nt][2], Dacc[nt][3]);
    }
}

extern "C" void kernel_launch(void* const* d_in, const int* in_sizes, int n_in,
                              void* d_out, int out_size)
{
    const float* points   = (const float*)d_in[0];
    const float* features = (const float*)d_in[1];
    const float* outpts   = (const float*)d_in[2];
    const int*   nbr      = (const int*)  d_in[3];
    const float* kpts     = (const float*)d_in[4];
    const float* kvals    = (const float*)d_in[5];

    bfrag_prep<<<KP, 64>>>(kvals);

    cudaFuncSetAttribute(kpconv_mma, cudaFuncAttributeMaxDynamicSharedMemorySize, SMEM_TOTAL);
    kpconv_mma<<<GRID, THREADS, SMEM_TOTAL>>>(points, features, outpts, nbr, kpts, (float*)d_out);
}